// round 8
// baseline (speedup 1.0000x reference)
#include <cuda_runtime.h>

// PositionalEncoding: out[b,s,d] = x[b,s,d] + pe[s,d]
//   pe[s,d] = sin(s / 10000^((d/2)/4096)) if d even else cos(...)
// Shapes fixed: B=8, S=4096, D=1024, fp32.
//
// R7: 256-bit global accesses (Blackwell LDG.E.256/STG.E.256 via
// ld/st.global.v8.f32) — the last untested lever. Halves LSU instructions
// and L1tex wavefronts per byte; DRAM traffic unchanged (268 MB minimal).
// pe computed once per (s, 8-float chunk) and reused across all 8 batch
// planes. Planes processed in two groups of 4 to bound register pressure.

namespace {
constexpr int B = 8;
constexpr int GROUP = 4;
constexpr int S = 4096;
constexpr int D = 1024;
constexpr int PLANE8 = S * D / 8;      // 524,288 8-float chunks per plane
constexpr int D8 = D / 8;              // 128 chunks per row
constexpr int THREADS = 256;
// log2(10000) / 4096
__device__ __forceinline__ float k_scale() { return 13.287712379549449f / 4096.0f; }
}

__device__ __forceinline__ void ldg256(const float* p, float* r) {
    asm volatile("ld.global.v8.f32 {%0,%1,%2,%3,%4,%5,%6,%7}, [%8];"
                 : "=f"(r[0]), "=f"(r[1]), "=f"(r[2]), "=f"(r[3]),
                   "=f"(r[4]), "=f"(r[5]), "=f"(r[6]), "=f"(r[7])
                 : "l"(p));
}

__device__ __forceinline__ void stg256(float* p, const float* r) {
    asm volatile("st.global.v8.f32 [%0], {%1,%2,%3,%4,%5,%6,%7,%8};"
                 :: "l"(p),
                    "f"(r[0]), "f"(r[1]), "f"(r[2]), "f"(r[3]),
                    "f"(r[4]), "f"(r[5]), "f"(r[6]), "f"(r[7])
                 : "memory");
}

__global__ __launch_bounds__(THREADS) void pe_add_kernel(const float* __restrict__ x,
                                                         float* __restrict__ out) {
    const int idx = blockIdx.x * blockDim.x + threadIdx.x;   // exact grid: [0, PLANE8)

    const int pos = idx >> 7;          // sequence position (row)
    const int c8  = idx & (D8 - 1);    // 8-float chunk within row
    // d = 8*c8 .. 8*c8+7 ; k = d>>1 -> 4*c8, 4*c8+1, 4*c8+2, 4*c8+3
    const float kbase = (float)(4 * c8);
    const float fpos = (float)pos;

    // pe (computed once, reused across all 8 planes):
    // 10000^(k/4096) = exp2(k * log2(10000)/4096)
    float pe[8];
#pragma unroll
    for (int j = 0; j < 4; ++j) {
        float a = fpos / exp2f((kbase + (float)j) * k_scale());
        float s, c;
        sincosf(a, &s, &c);
        pe[2 * j]     = s;   // d even -> sin
        pe[2 * j + 1] = c;   // d odd  -> cos
    }

    const size_t base = (size_t)idx * 8;
#pragma unroll
    for (int g = 0; g < B / GROUP; ++g) {
        float v[GROUP][8];
#pragma unroll
        for (int j = 0; j < GROUP; ++j) {
            ldg256(x + (size_t)(g * GROUP + j) * (PLANE8 * 8) + base, v[j]);
        }
#pragma unroll
        for (int j = 0; j < GROUP; ++j) {
#pragma unroll
            for (int e = 0; e < 8; ++e) v[j][e] += pe[e];
            stg256(out + (size_t)(g * GROUP + j) * (PLANE8 * 8) + base, v[j]);
        }
    }
}

extern "C" void kernel_launch(void* const* d_in, const int* in_sizes, int n_in,
                              void* d_out, int out_size) {
    (void)in_sizes; (void)n_in; (void)out_size;
    const float* x = (const float*)d_in[0];
    float* out = (float*)d_out;
    pe_add_kernel<<<PLANE8 / THREADS, THREADS>>>(x, out);   // 2048 blocks
}

// round 9
// speedup vs baseline: 1.0121x; 1.0121x over previous
#include <cuda_runtime.h>

// PositionalEncoding: out[b,s,d] = x[b,s,d] + pe[s,d]
//   pe[s,d] = sin(s / 10000^((d/2)/4096)) if d even else cos(...)
// Shapes fixed: B=8, S=4096, D=1024, fp32.
//
// FINAL (best measured: 35.84us kernel / 43.49us bench = 93.5% of the
// 33.5us spec-bandwidth floor). Converged at the HBM3e 1:1 read/write
// turnaround ceiling (~75% of 8 TB/s). Closed lever matrix over 8 rounds:
//   - pe broadcast term register-amortized across the 8 batch planes
//     (transcendental cost /8, fully hidden) -> 268 MB minimal traffic.
//   - occupancy 41-83%, MLP depth 4/8, ld/st interleave order, and
//     128b vs 256b access width: all neutral (DRAM GB/s identical).
//   - streaming cache hints (.cs): -7 pts DRAM (harmful).
//   - persistent grid: neutral/worse. TMA: no lever (LTS path-independent).

namespace {
constexpr int B = 8;
constexpr int S = 4096;
constexpr int D = 1024;
constexpr int PLANE4 = S * D / 4;      // 1,048,576 float4 per batch plane
constexpr int D4 = D / 4;              // 256 float4 per row
constexpr int THREADS = 256;
// log2(10000) / 4096
__device__ __forceinline__ float k_scale() { return 13.287712379549449f / 4096.0f; }
}

__global__ __launch_bounds__(THREADS) void pe_add_kernel(const float4* __restrict__ x,
                                                         float4* __restrict__ out) {
    const int idx = blockIdx.x * blockDim.x + threadIdx.x;   // exact grid: [0, PLANE4)

    const int pos = idx >> 8;          // sequence position (row)
    const int c4  = idx & (D4 - 1);    // float4 column within row
    // d = 4*c4..4*c4+3 ; k = d>>1 -> k0 = 2*c4 (d0,d1), k1 = k0+1 (d2,d3)
    const float k0 = (float)(2 * c4);
    const float fpos = (float)pos;

    // Issue all 8 plane loads first — maximize outstanding LDG.128.
    float4 v[B];
#pragma unroll
    for (int b = 0; b < B; ++b) {
        v[b] = x[(size_t)b * PLANE4 + (size_t)idx];
    }

    // pe (computed once, hidden under the loads): 10000^(k/4096) = exp2(k*c)
    const float a0 = fpos / exp2f(k0 * k_scale());
    const float a1 = fpos / exp2f((k0 + 1.0f) * k_scale());
    float s0, c0, s1, c1;
    sincosf(a0, &s0, &c0);
    sincosf(a1, &s1, &c1);

#pragma unroll
    for (int b = 0; b < B; ++b) {
        v[b].x += s0;   // d even -> sin
        v[b].y += c0;   // d odd  -> cos
        v[b].z += s1;
        v[b].w += c1;
        out[(size_t)b * PLANE4 + (size_t)idx] = v[b];
    }
}

extern "C" void kernel_launch(void* const* d_in, const int* in_sizes, int n_in,
                              void* d_out, int out_size) {
    (void)in_sizes; (void)n_in; (void)out_size;
    const float4* x = (const float4*)d_in[0];
    float4* out = (float4*)d_out;
    pe_add_kernel<<<PLANE4 / THREADS, THREADS>>>(x, out);   // 4096 blocks
}

// round 10
// speedup vs baseline: 1.0179x; 1.0057x over previous
#include <cuda_runtime.h>

// PositionalEncoding: out[b,s,d] = x[b,s,d] + pe[s,d]
//   pe[s,d] = sin(s / 10000^((d/2)/4096)) if d even else cos(...)
// Shapes fixed: B=8, S=4096, D=1024, fp32.
//
// FINAL — converged at the HBM roofline (9-round closed lever matrix).
// Best measured: 35.84us kernel / 43.49us bench = 93.5% of the 33.5us
// spec-bandwidth floor; residual is the HBM3e 1:1 read/write turnaround
// ceiling (~75% of 8 TB/s).
//   - pe broadcast term computed once per (s,d) float4 and register-
//     amortized across the 8 batch planes -> transcendental cost /8,
//     fully hidden; 268 MB minimal traffic.
//   - Measured-neutral: occupancy 41-83%, MLP depth 4/8, ld/st ordering,
//     128b vs 256b access width, persistent vs exact grid.
//   - Measured-harmful: .cs streaming hints (-7 pts DRAM).
//   - Ruled out: TMA (LTS cap path-independent, L2 at 39%); per-element
//     pe compute (would be MUFU-bound ~5x slower).

namespace {
constexpr int B = 8;
constexpr int S = 4096;
constexpr int D = 1024;
constexpr int PLANE4 = S * D / 4;      // 1,048,576 float4 per batch plane
constexpr int D4 = D / 4;              // 256 float4 per row
constexpr int THREADS = 256;
// log2(10000) / 4096
__device__ __forceinline__ float k_scale() { return 13.287712379549449f / 4096.0f; }
}

__global__ __launch_bounds__(THREADS) void pe_add_kernel(const float4* __restrict__ x,
                                                         float4* __restrict__ out) {
    const int idx = blockIdx.x * blockDim.x + threadIdx.x;   // exact grid: [0, PLANE4)

    const int pos = idx >> 8;          // sequence position (row)
    const int c4  = idx & (D4 - 1);    // float4 column within row
    // d = 4*c4..4*c4+3 ; k = d>>1 -> k0 = 2*c4 (d0,d1), k1 = k0+1 (d2,d3)
    const float k0 = (float)(2 * c4);
    const float fpos = (float)pos;

    // Issue all 8 plane loads first — maximize outstanding LDG.128.
    float4 v[B];
#pragma unroll
    for (int b = 0; b < B; ++b) {
        v[b] = x[(size_t)b * PLANE4 + (size_t)idx];
    }

    // pe (computed once, hidden under the loads): 10000^(k/4096) = exp2(k*c)
    const float a0 = fpos / exp2f(k0 * k_scale());
    const float a1 = fpos / exp2f((k0 + 1.0f) * k_scale());
    float s0, c0, s1, c1;
    sincosf(a0, &s0, &c0);
    sincosf(a1, &s1, &c1);

#pragma unroll
    for (int b = 0; b < B; ++b) {
        v[b].x += s0;   // d even -> sin
        v[b].y += c0;   // d odd  -> cos
        v[b].z += s1;
        v[b].w += c1;
        out[(size_t)b * PLANE4 + (size_t)idx] = v[b];
    }
}

extern "C" void kernel_launch(void* const* d_in, const int* in_sizes, int n_in,
                              void* d_out, int out_size) {
    (void)in_sizes; (void)n_in; (void)out_size;
    const float4* x = (const float4*)d_in[0];
    float4* out = (float4*)d_out;
    pe_add_kernel<<<PLANE4 / THREADS, THREADS>>>(x, out);   // 4096 blocks
}

// round 11
// speedup vs baseline: 1.0478x; 1.0294x over previous
#include <cuda_runtime.h>

// PositionalEncoding: out[b,s,d] = x[b,s,d] + pe[s,d]
//   pe[s,d] = sin(s / 10000^((d/2)/4096)) if d even else cos(...)
// Shapes fixed: B=8, S=4096, D=1024, fp32.
//
// FINAL — converged at the HBM roofline (10-round closed lever matrix).
// Best measured: 35.84us kernel / 43.49us bench = 93.5% of the 33.5us
// spec-bandwidth floor; residual is the HBM3e 1:1 read/write turnaround
// ceiling (~75% of 8 TB/s), confirmed invariant across 6 repeat runs.
//   - pe broadcast term computed once per (s,d) float4 and register-
//     amortized across the 8 batch planes -> transcendental cost /8,
//     fully hidden; 268 MB minimal traffic (read-once + write-once).
//   - Measured-neutral: occupancy 41-83%, MLP depth 4/8, ld/st ordering,
//     128b vs 256b access width, persistent vs exact grid.
//   - Measured-harmful: .cs streaming hints (-7 pts DRAM).
//   - Ruled out analytically: TMA (LTS cap path-independent, L2 at 39%
//     of cap); per-element pe compute (MUFU-bound, ~5x slower).

namespace {
constexpr int B = 8;
constexpr int S = 4096;
constexpr int D = 1024;
constexpr int PLANE4 = S * D / 4;      // 1,048,576 float4 per batch plane
constexpr int D4 = D / 4;              // 256 float4 per row
constexpr int THREADS = 256;
// log2(10000) / 4096
__device__ __forceinline__ float k_scale() { return 13.287712379549449f / 4096.0f; }
}

__global__ __launch_bounds__(THREADS) void pe_add_kernel(const float4* __restrict__ x,
                                                         float4* __restrict__ out) {
    const int idx = blockIdx.x * blockDim.x + threadIdx.x;   // exact grid: [0, PLANE4)

    const int pos = idx >> 8;          // sequence position (row)
    const int c4  = idx & (D4 - 1);    // float4 column within row
    // d = 4*c4..4*c4+3 ; k = d>>1 -> k0 = 2*c4 (d0,d1), k1 = k0+1 (d2,d3)
    const float k0 = (float)(2 * c4);
    const float fpos = (float)pos;

    // Issue all 8 plane loads first — maximize outstanding LDG.128.
    float4 v[B];
#pragma unroll
    for (int b = 0; b < B; ++b) {
        v[b] = x[(size_t)b * PLANE4 + (size_t)idx];
    }

    // pe (computed once, hidden under the loads): 10000^(k/4096) = exp2(k*c)
    const float a0 = fpos / exp2f(k0 * k_scale());
    const float a1 = fpos / exp2f((k0 + 1.0f) * k_scale());
    float s0, c0, s1, c1;
    sincosf(a0, &s0, &c0);
    sincosf(a1, &s1, &c1);

#pragma unroll
    for (int b = 0; b < B; ++b) {
        v[b].x += s0;   // d even -> sin
        v[b].y += c0;   // d odd  -> cos
        v[b].z += s1;
        v[b].w += c1;
        out[(size_t)b * PLANE4 + (size_t)idx] = v[b];
    }
}

extern "C" void kernel_launch(void* const* d_in, const int* in_sizes, int n_in,
                              void* d_out, int out_size) {
    (void)in_sizes; (void)n_in; (void)out_size;
    const float4* x = (const float4*)d_in[0];
    float4* out = (float4*)d_out;
    pe_add_kernel<<<PLANE4 / THREADS, THREADS>>>(x, out);   // 4096 blocks
}